// round 3
// baseline (speedup 1.0000x reference)
#include <cuda_runtime.h>
#include <math.h>

#define B_   2
#define T_   2048
#define D_   1024
#define NH_  16
#define NKV_ 4
#define HD_  64
#define KD_  256
#define FULLMASK 0xffffffffu

// ---------------- scratch (device globals; no runtime alloc) ----------------
__device__ float g_Wq_eff[D_ * D_];        // 4 MB
__device__ float g_Wv_eff[KD_ * D_];       // 1 MB
__device__ float g_q[B_ * T_ * D_];        // 16 MB  (B*T, D) pre-norm q
__device__ float g_k[B_ * T_ * KD_];       // 4 MB
__device__ float g_v[B_ * T_ * KD_];       // 4 MB
__device__ float g_qh[B_ * NH_ * T_ * HD_];  // 16 MB  [b][h][t][d]
__device__ float g_kh[B_ * NKV_ * T_ * HD_]; // 4 MB
__device__ float g_vh[B_ * NKV_ * T_ * HD_]; // 4 MB
__device__ float g_y[B_ * T_ * D_];        // 16 MB  attention output (B,T,D)

// ---------------- W_eff = W + Bmat @ Amat (rank 8, ALPHA=1) ----------------
__global__ __launch_bounds__(256) void lora_fuse(
    const float* __restrict__ W, const float* __restrict__ Bm,
    const float* __restrict__ Am, float* __restrict__ Weff, int N, int K) {
    int idx = blockIdx.x * 256 + threadIdx.x;
    if (idx >= N * K) return;
    int n = idx / K, k = idx - n * K;
    float acc = W[idx];
#pragma unroll
    for (int r = 0; r < 8; r++) acc += Bm[n * 8 + r] * Am[r * K + k];
    Weff[idx] = acc;
}

// ---------------- C[M,N] = A[M,K] @ B[N,K]^T  (fp32 tiled) ----------------
// BM=BN=64, BK=16, 256 threads, 4x4 microtile per thread.
__global__ __launch_bounds__(256) void gemm_nt(
    const float* __restrict__ A, const float* __restrict__ B,
    float* __restrict__ C, int M, int N, int K) {
    __shared__ float As[16 * 64];  // [kk][m]
    __shared__ float Bs[16 * 64];  // [kk][n]
    int tid = threadIdx.x;
    int tx = tid & 15, ty = tid >> 4;
    int bx = blockIdx.x, by = blockIdx.y;
    const float* Ab = A + (size_t)by * 64 * K;
    const float* Bb = B + (size_t)bx * 64 * K;
    float acc[4][4];
#pragma unroll
    for (int i = 0; i < 4; i++)
#pragma unroll
        for (int j = 0; j < 4; j++) acc[i][j] = 0.f;

    int lr = tid >> 2;              // 0..63
    int lc = (tid & 3) << 2;        // 0,4,8,12

    for (int k0 = 0; k0 < K; k0 += 16) {
        float4 av = *reinterpret_cast<const float4*>(Ab + (size_t)lr * K + k0 + lc);
        float4 bv = *reinterpret_cast<const float4*>(Bb + (size_t)lr * K + k0 + lc);
        As[(lc + 0) * 64 + lr] = av.x; As[(lc + 1) * 64 + lr] = av.y;
        As[(lc + 2) * 64 + lr] = av.z; As[(lc + 3) * 64 + lr] = av.w;
        Bs[(lc + 0) * 64 + lr] = bv.x; Bs[(lc + 1) * 64 + lr] = bv.y;
        Bs[(lc + 2) * 64 + lr] = bv.z; Bs[(lc + 3) * 64 + lr] = bv.w;
        __syncthreads();
#pragma unroll
        for (int kk = 0; kk < 16; kk++) {
            float4 a = *reinterpret_cast<const float4*>(&As[kk * 64 + ty * 4]);
            float4 b = *reinterpret_cast<const float4*>(&Bs[kk * 64 + tx * 4]);
            float ar[4] = {a.x, a.y, a.z, a.w};
            float br[4] = {b.x, b.y, b.z, b.w};
#pragma unroll
            for (int i = 0; i < 4; i++)
#pragma unroll
                for (int j = 0; j < 4; j++) acc[i][j] += ar[i] * br[j];
        }
        __syncthreads();
    }
#pragma unroll
    for (int i = 0; i < 4; i++) {
        size_t row = (size_t)by * 64 + ty * 4 + i;
        float4 o = make_float4(acc[i][0], acc[i][1], acc[i][2], acc[i][3]);
        *reinterpret_cast<float4*>(C + row * N + bx * 64 + tx * 4) = o;
    }
}

// ---------------- RoPE helpers ----------------
__device__ __forceinline__ void rope_cs(int t, int j, float& c, float& s) {
    // inv = 1 / 10000^(2j/16), fp32 like the reference
    float e = (2.0f * (float)j) / 16.0f;
    float inv = 1.0f / powf(10000.0f, e);
    float f = (float)t * inv;
    c = cosf(f);
    s = sinf(f);
}

// Normalize (RMS over 64) + partial RoPE (PD=16) + scale; one warp per row.
// lane holds dims 2*lane, 2*lane+1.
__device__ __forceinline__ void norm_rope_row(
    const float* __restrict__ src, float* __restrict__ dst,
    int t, float scale, int lane) {
    float2 v = *reinterpret_cast<const float2*>(src + lane * 2);
    float ss = v.x * v.x + v.y * v.y;
#pragma unroll
    for (int o = 16; o; o >>= 1) ss += __shfl_xor_sync(FULLMASK, ss, o);
    float rms = rsqrtf(ss * (1.0f / 64.0f) + 1.1920929e-7f);
    float v0 = v.x * rms, v1 = v.y * rms;
    float u0 = __shfl_xor_sync(FULLMASK, v0, 4);
    float u1 = __shfl_xor_sync(FULLMASK, v1, 4);
    int d0 = lane * 2;
    if (d0 < 8) {            // x1 role: out = x1*c + x2*s, j = d
        float c0, s0, c1, s1;
        rope_cs(t, d0, c0, s0);
        rope_cs(t, d0 + 1, c1, s1);
        v0 = v0 * c0 + u0 * s0;
        v1 = v1 * c1 + u1 * s1;
    } else if (d0 < 16) {    // x2 role: out = -x2*c + x1*s, j = d-8
        float c0, s0, c1, s1;
        rope_cs(t, d0 - 8, c0, s0);
        rope_cs(t, d0 - 7, c1, s1);
        v0 = -v0 * c0 + u0 * s0;
        v1 = -v1 * c1 + u1 * s1;
    }
    *reinterpret_cast<float2*>(dst + lane * 2) = make_float2(v0 * scale, v1 * scale);
}

// q: rms + rope + gain*softmax_scale, and transpose (B,T,NH,HD)->(B,NH,T,HD)
__global__ __launch_bounds__(256) void q_prep(
    const float* __restrict__ Qin, const float* __restrict__ qgain,
    float* __restrict__ Qout) {
    int warp = (blockIdx.x * 256 + threadIdx.x) >> 5;
    int lane = threadIdx.x & 31;
    if (warp >= B_ * T_ * NH_) return;
    int h = warp & 15;
    int t = (warp >> 4) & 2047;
    int b = warp >> 15;
    const float* src = Qin + ((size_t)(b * T_ + t)) * D_ + h * HD_;
    float* dst = Qout + (((size_t)(b * NH_ + h)) * T_ + t) * HD_;
    float scale = qgain[h] * 0.125f;  // gain * 1/sqrt(64)
    norm_rope_row(src, dst, t, scale, lane);
}

// k: rms + rope, transpose; v: straight transpose
__global__ __launch_bounds__(256) void kv_prep(
    const float* __restrict__ Kin, const float* __restrict__ Vin,
    float* __restrict__ Kout, float* __restrict__ Vout) {
    int warp = (blockIdx.x * 256 + threadIdx.x) >> 5;
    int lane = threadIdx.x & 31;
    if (warp >= B_ * T_ * NKV_) return;
    int hk = warp & 3;
    int t = (warp >> 2) & 2047;
    int b = warp >> 13;
    const float* ksrc = Kin + ((size_t)(b * T_ + t)) * KD_ + hk * HD_;
    float* kdst = Kout + (((size_t)(b * NKV_ + hk)) * T_ + t) * HD_;
    norm_rope_row(ksrc, kdst, t, 1.0f, lane);
    const float* vsrc = Vin + ((size_t)(b * T_ + t)) * KD_ + hk * HD_;
    float* vdst = Vout + (((size_t)(b * NKV_ + hk)) * T_ + t) * HD_;
    *reinterpret_cast<float2*>(vdst + lane * 2) =
        *reinterpret_cast<const float2*>(vsrc + lane * 2);
}

// ---------------- causal flash attention, fp32 ----------------
// grid (T/64, B*NH), block 256. 64-query tile, 64-key tiles, online softmax.
// smem: Qs[d][r] 16KB, Ks[d][c] 16KB, Vs[j][d] 16KB, Ps[r][c] 16KB.
__global__ __launch_bounds__(256) void attn_kernel(
    const float* __restrict__ Qh, const float* __restrict__ Kh,
    const float* __restrict__ Vh, float* __restrict__ Y) {
    extern __shared__ float sm[];
    float* Qs = sm;
    float* Ks = sm + 4096;
    float* Vs = sm + 8192;
    float* Ps = sm + 12288;
    int tid = threadIdx.x;
    int tx = tid & 15, ty = tid >> 4;
    int bh = blockIdx.y;
    int b = bh >> 4, h = bh & 15;
    int i0 = ((int)gridDim.x - 1 - (int)blockIdx.x) * 64;  // reversed for balance
    int kvh = h >> 2;
    const float* Qg = Qh + (((size_t)(b * NH_ + h)) * T_ + i0) * HD_;
    const float* Kg = Kh + ((size_t)(b * NKV_ + kvh)) * T_ * HD_;
    const float* Vg = Vh + ((size_t)(b * NKV_ + kvh)) * T_ * HD_;

    // load Q tile transposed: Qs[d][r]
#pragma unroll
    for (int tloop = 0; tloop < 4; tloop++) {
        int idx = tid + tloop * 256;          // float4 index 0..1023
        int r = idx >> 4, d4 = (idx & 15) << 2;
        float4 q4 = *reinterpret_cast<const float4*>(Qg + r * 64 + d4);
        Qs[(d4 + 0) * 64 + r] = q4.x; Qs[(d4 + 1) * 64 + r] = q4.y;
        Qs[(d4 + 2) * 64 + r] = q4.z; Qs[(d4 + 3) * 64 + r] = q4.w;
    }

    float m[4], l[4], acc[4][4];
#pragma unroll
    for (int i = 0; i < 4; i++) {
        m[i] = -1e30f; l[i] = 0.f;
#pragma unroll
        for (int j = 0; j < 4; j++) acc[i][j] = 0.f;
    }

    int ntiles = i0 / 64 + 1;
    for (int kt = 0; kt < ntiles; kt++) {
        int j0 = kt * 64;
        __syncthreads();  // smem safe to overwrite (and Q visible on iter 0 after next sync)
        // load K transposed (Ks[d][c]) and V natural (Vs[j][d])
#pragma unroll
        for (int tloop = 0; tloop < 4; tloop++) {
            int idx = tid + tloop * 256;
            int c = idx >> 4, d4 = (idx & 15) << 2;
            float4 k4 = *reinterpret_cast<const float4*>(Kg + (j0 + c) * 64 + d4);
            Ks[(d4 + 0) * 64 + c] = k4.x; Ks[(d4 + 1) * 64 + c] = k4.y;
            Ks[(d4 + 2) * 64 + c] = k4.z; Ks[(d4 + 3) * 64 + c] = k4.w;
            *reinterpret_cast<float4*>(Vs + idx * 4) =
                *reinterpret_cast<const float4*>(Vg + j0 * 64 + idx * 4);
        }
        __syncthreads();

        // S = Q K^T  (scale already folded into q)
        float s[4][4];
#pragma unroll
        for (int i = 0; i < 4; i++)
#pragma unroll
            for (int j = 0; j < 4; j++) s[i][j] = 0.f;
#pragma unroll 8
        for (int d = 0; d < 64; d++) {
            float4 a = *reinterpret_cast<const float4*>(&Qs[d * 64 + ty * 4]);
            float4 k4 = *reinterpret_cast<const float4*>(&Ks[d * 64 + tx * 4]);
            float ar[4] = {a.x, a.y, a.z, a.w};
            float br[4] = {k4.x, k4.y, k4.z, k4.w};
#pragma unroll
            for (int i = 0; i < 4; i++)
#pragma unroll
                for (int j = 0; j < 4; j++) s[i][j] += ar[i] * br[j];
        }
        if (j0 == i0) {  // diagonal tile: mask col > row
#pragma unroll
            for (int i = 0; i < 4; i++)
#pragma unroll
                for (int j = 0; j < 4; j++)
                    if (tx * 4 + j > ty * 4 + i) s[i][j] = -1e30f;
        }

        // online softmax update
        float sf[4], rs[4];
#pragma unroll
        for (int i = 0; i < 4; i++) {
            float tmax = fmaxf(fmaxf(s[i][0], s[i][1]), fmaxf(s[i][2], s[i][3]));
#pragma unroll
            for (int o = 8; o; o >>= 1)
                tmax = fmaxf(tmax, __shfl_xor_sync(FULLMASK, tmax, o));
            float mn = fmaxf(m[i], tmax);
            sf[i] = __expf(m[i] - mn);
            m[i] = mn;
            float r = 0.f;
#pragma unroll
            for (int j = 0; j < 4; j++) {
                float p = __expf(s[i][j] - mn);
                s[i][j] = p;
                r += p;
            }
#pragma unroll
            for (int o = 8; o; o >>= 1) r += __shfl_xor_sync(FULLMASK, r, o);
            rs[i] = r;
        }
#pragma unroll
        for (int i = 0; i < 4; i++) {
            l[i] = l[i] * sf[i] + rs[i];
#pragma unroll
            for (int j = 0; j < 4; j++) acc[i][j] *= sf[i];
            *reinterpret_cast<float4*>(&Ps[(ty * 4 + i) * 64 + tx * 4]) =
                make_float4(s[i][0], s[i][1], s[i][2], s[i][3]);
        }
        __syncthreads();

        // acc += P @ V
#pragma unroll 8
        for (int j = 0; j < 64; j++) {
            float4 v4 = *reinterpret_cast<const float4*>(&Vs[j * 64 + tx * 4]);
            float vr[4] = {v4.x, v4.y, v4.z, v4.w};
            float a0 = Ps[(ty * 4 + 0) * 64 + j];
            float a1 = Ps[(ty * 4 + 1) * 64 + j];
            float a2 = Ps[(ty * 4 + 2) * 64 + j];
            float a3 = Ps[(ty * 4 + 3) * 64 + j];
#pragma unroll
            for (int jj = 0; jj < 4; jj++) {
                acc[0][jj] += a0 * vr[jj];
                acc[1][jj] += a1 * vr[jj];
                acc[2][jj] += a2 * vr[jj];
                acc[3][jj] += a3 * vr[jj];
            }
        }
    }

    // epilogue: normalize and write y[b][t][h*64+d]
#pragma unroll
    for (int i = 0; i < 4; i++) {
        float inv_l = 1.0f / l[i];
        int row = i0 + ty * 4 + i;
        float4 o = make_float4(acc[i][0] * inv_l, acc[i][1] * inv_l,
                               acc[i][2] * inv_l, acc[i][3] * inv_l);
        *reinterpret_cast<float4*>(Y + ((size_t)b * T_ + row) * D_ + h * HD_ + tx * 4) = o;
    }
}

// ---------------- launch ----------------
extern "C" void kernel_launch(void* const* d_in, const int* in_sizes, int n_in,
                              void* d_out, int out_size) {
    const float* x     = (const float*)d_in[0];
    const float* Wq    = (const float*)d_in[1];
    const float* Wk    = (const float*)d_in[2];
    const float* Wv    = (const float*)d_in[3];
    const float* Wproj = (const float*)d_in[4];
    const float* qg    = (const float*)d_in[5];
    const float* Aq    = (const float*)d_in[6];
    const float* Bq    = (const float*)d_in[7];
    const float* Av    = (const float*)d_in[8];
    const float* Bv    = (const float*)d_in[9];
    float* out = (float*)d_out;

    float *pWqe, *pWve, *pq, *pk, *pv, *pqh, *pkh, *pvh, *py;
    cudaGetSymbolAddress((void**)&pWqe, g_Wq_eff);
    cudaGetSymbolAddress((void**)&pWve, g_Wv_eff);
    cudaGetSymbolAddress((void**)&pq, g_q);
    cudaGetSymbolAddress((void**)&pk, g_k);
    cudaGetSymbolAddress((void**)&pv, g_v);
    cudaGetSymbolAddress((void**)&pqh, g_qh);
    cudaGetSymbolAddress((void**)&pkh, g_kh);
    cudaGetSymbolAddress((void**)&pvh, g_vh);
    cudaGetSymbolAddress((void**)&py, g_y);

    // 1. fold LoRA into weights
    lora_fuse<<<(D_ * D_) / 256, 256>>>(Wq, Bq, Aq, pWqe, D_, D_);
    lora_fuse<<<(KD_ * D_) / 256, 256>>>(Wv, Bv, Av, pWve, KD_, D_);

    // 2. projections
    dim3 gq(D_ / 64, (B_ * T_) / 64);
    dim3 gk(KD_ / 64, (B_ * T_) / 64);
    gemm_nt<<<gq, 256>>>(x, pWqe, pq, B_ * T_, D_, D_);
    gemm_nt<<<gk, 256>>>(x, Wk, pk, B_ * T_, KD_, D_);
    gemm_nt<<<gk, 256>>>(x, pWve, pv, B_ * T_, KD_, D_);

    // 3. norm + rope + transpose
    q_prep<<<(B_ * T_ * NH_) / 8, 256>>>(pq, qg, pqh);
    kv_prep<<<(B_ * T_ * NKV_) / 8, 256>>>(pk, pv, pkh, pvh);

    // 4. attention
    cudaFuncSetAttribute(attn_kernel,
                         cudaFuncAttributeMaxDynamicSharedMemorySize, 65536);
    dim3 ga(T_ / 64, B_ * NH_);
    attn_kernel<<<ga, 256, 65536>>>(pqh, pkh, pvh, py);

    // 5. output projection
    gemm_nt<<<gq, 256>>>(py, Wproj, out, B_ * T_, D_, D_);
}

// round 9
// speedup vs baseline: 1.1644x; 1.1644x over previous
#include <cuda_runtime.h>
#include <math.h>

#define B_   2
#define T_   2048
#define D_   1024
#define NH_  16
#define NKV_ 4
#define HD_  64
#define KD_  256
#define KV2_ 512
#define FULLMASK 0xffffffffu

typedef unsigned long long ull;

// ---------------- f32x2 packed helpers ----------------
__device__ __forceinline__ ull ffma2(ull a, ull b, ull c) {
    ull d;
    asm("fma.rn.f32x2 %0, %1, %2, %3;" : "=l"(d) : "l"(a), "l"(b), "l"(c));
    return d;
}
__device__ __forceinline__ ull fmul2(ull a, ull b) {
    ull d;
    asm("mul.rn.f32x2 %0, %1, %2;" : "=l"(d) : "l"(a), "l"(b));
    return d;
}
__device__ __forceinline__ ull fdup2(float x) {
    ull r;
    asm("mov.b64 %0, {%1, %1};" : "=l"(r) : "f"(x));
    return r;
}
__device__ __forceinline__ void funpack2(float& lo, float& hi, ull v) {
    asm("mov.b64 {%0, %1}, %2;" : "=f"(lo), "=f"(hi) : "l"(v));
}

// ---------------- scratch (device globals; no runtime alloc) ----------------
__device__ float g_Wq_eff[D_ * D_];
__device__ float g_Wkv[KV2_ * D_];           // rows 0..255 = Wk, 256..511 = Wv_eff
__device__ float g_q[B_ * T_ * D_];
__device__ float g_kv[B_ * T_ * KV2_];
__device__ float g_qh[B_ * NH_ * T_ * HD_];  // [b][h][t][d]
__device__ float g_kh[B_ * NKV_ * T_ * HD_];
__device__ float g_vh[B_ * NKV_ * T_ * HD_];
__device__ float g_y[B_ * T_ * D_];

// ---------------- Wq_eff = Wq + Bq @ Aq ----------------
__global__ __launch_bounds__(256) void lora_fuse(
    const float* __restrict__ W, const float* __restrict__ Bm,
    const float* __restrict__ Am, float* __restrict__ Weff, int N, int K) {
    int idx = blockIdx.x * 256 + threadIdx.x;
    if (idx >= N * K) return;
    int n = idx / K, k = idx - n * K;
    float acc = W[idx];
#pragma unroll
    for (int r = 0; r < 8; r++) acc += Bm[n * 8 + r] * Am[r * K + k];
    Weff[idx] = acc;
}

// ---------------- Wkv: rows [0,256)=Wk, [256,512)=Wv + Bv@Av ----------------
__global__ __launch_bounds__(256) void build_wkv(
    const float* __restrict__ Wk, const float* __restrict__ Wv,
    const float* __restrict__ Bv, const float* __restrict__ Av,
    float* __restrict__ Wkv) {
    int idx = blockIdx.x * 256 + threadIdx.x;
    if (idx >= KV2_ * D_) return;
    int n = idx >> 10, k = idx & 1023;
    if (n < KD_) {
        Wkv[idx] = Wk[n * D_ + k];
    } else {
        int nv = n - KD_;
        float acc = Wv[nv * D_ + k];
#pragma unroll
        for (int r = 0; r < 8; r++) acc += Bv[nv * 8 + r] * Av[r * D_ + k];
        Wkv[idx] = acc;
    }
}

// ---------------- C[M,N] = A[M,K] @ B[N,K]^T, fp32 via FFMA2 ----------------
// 128x128 tile, BK=16, 256 threads (16x16), 8x8 microtile.
// Plain smem (no duplication); B read as natural col-pairs, A dup'd in regs.
__global__ __launch_bounds__(256, 2) void gemm_nt_f2(
    const float* __restrict__ A, const float* __restrict__ B,
    float* __restrict__ C, int M, int N, int K) {
    __shared__ float As[16 * 128];  // [kk][m]
    __shared__ float Bs[16 * 128];  // [kk][n]
    int tid = threadIdx.x;
    int tx = tid & 15, ty = tid >> 4;
    const float* Ab = A + (size_t)(blockIdx.y * 128) * K;
    const float* Bb = B + (size_t)(blockIdx.x * 128) * K;
    int lr = tid >> 2;            // 0..63
    int lc = (tid & 3) << 2;      // 0,4,8,12

    ull acc[8][4];
#pragma unroll
    for (int i = 0; i < 8; i++)
#pragma unroll
        for (int j = 0; j < 4; j++) acc[i][j] = 0ull;

    float4 av0 = *reinterpret_cast<const float4*>(Ab + (size_t)lr * K + lc);
    float4 av1 = *reinterpret_cast<const float4*>(Ab + (size_t)(lr + 64) * K + lc);
    float4 bv0 = *reinterpret_cast<const float4*>(Bb + (size_t)lr * K + lc);
    float4 bv1 = *reinterpret_cast<const float4*>(Bb + (size_t)(lr + 64) * K + lc);

    for (int k0 = 0; k0 < K; k0 += 16) {
        __syncthreads();
        {
            float a0[4] = {av0.x, av0.y, av0.z, av0.w};
            float a1[4] = {av1.x, av1.y, av1.z, av1.w};
            float b0[4] = {bv0.x, bv0.y, bv0.z, bv0.w};
            float b1[4] = {bv1.x, bv1.y, bv1.z, bv1.w};
#pragma unroll
            for (int c = 0; c < 4; c++) {
                As[(lc + c) * 128 + lr]      = a0[c];
                As[(lc + c) * 128 + lr + 64] = a1[c];
                Bs[(lc + c) * 128 + lr]      = b0[c];
                Bs[(lc + c) * 128 + lr + 64] = b1[c];
            }
        }
        __syncthreads();
        if (k0 + 16 < K) {
            av0 = *reinterpret_cast<const float4*>(Ab + (size_t)lr * K + k0 + 16 + lc);
            av1 = *reinterpret_cast<const float4*>(Ab + (size_t)(lr + 64) * K + k0 + 16 + lc);
            bv0 = *reinterpret_cast<const float4*>(Bb + (size_t)lr * K + k0 + 16 + lc);
            bv1 = *reinterpret_cast<const float4*>(Bb + (size_t)(lr + 64) * K + k0 + 16 + lc);
        }
#pragma unroll
        for (int kk = 0; kk < 16; kk++) {
            // rows: ty*4..+3 (group 0) and 64+ty*4..+3 (group 1) -- broadcast reads
            float4 a0 = *reinterpret_cast<const float4*>(&As[kk * 128 + ty * 4]);
            float4 a1 = *reinterpret_cast<const float4*>(&As[kk * 128 + 64 + ty * 4]);
            // cols: tx*4..+3 and 64+tx*4..+3 as natural ull pairs -- conflict-free
            ulonglong2 b0 = *reinterpret_cast<const ulonglong2*>(&Bs[kk * 128 + tx * 4]);
            ulonglong2 b1 = *reinterpret_cast<const ulonglong2*>(&Bs[kk * 128 + 64 + tx * 4]);
            ull bb[4] = {b0.x, b0.y, b1.x, b1.y};
            float av[8] = {a0.x, a0.y, a0.z, a0.w, a1.x, a1.y, a1.z, a1.w};
#pragma unroll
            for (int i = 0; i < 8; i++) {
                ull ai = fdup2(av[i]);
#pragma unroll
                for (int j = 0; j < 4; j++) acc[i][j] = ffma2(ai, bb[j], acc[i][j]);
            }
        }
    }

#pragma unroll
    for (int i = 0; i < 8; i++) {
        int rloc = (i < 4) ? (ty * 4 + i) : (64 + ty * 4 + i - 4);
        size_t row = (size_t)blockIdx.y * 128 + rloc;
        float c0, c1, c2, c3, c4, c5, c6, c7;
        funpack2(c0, c1, acc[i][0]);
        funpack2(c2, c3, acc[i][1]);
        funpack2(c4, c5, acc[i][2]);
        funpack2(c6, c7, acc[i][3]);
        float* Cp = C + row * N + blockIdx.x * 128;
        *reinterpret_cast<float4*>(Cp + tx * 4)      = make_float4(c0, c1, c2, c3);
        *reinterpret_cast<float4*>(Cp + 64 + tx * 4) = make_float4(c4, c5, c6, c7);
    }
}

// ---------------- RoPE helpers ----------------
__device__ __forceinline__ void rope_cs(int t, int j, float& c, float& s) {
    float e = (2.0f * (float)j) / 16.0f;
    float inv = 1.0f / powf(10000.0f, e);
    float f = (float)t * inv;
    c = cosf(f);
    s = sinf(f);
}

__device__ __forceinline__ void norm_rope_row(
    const float* __restrict__ src, float* __restrict__ dst,
    int t, float scale, int lane) {
    float2 v = *reinterpret_cast<const float2*>(src + lane * 2);
    float ss = v.x * v.x + v.y * v.y;
#pragma unroll
    for (int o = 16; o; o >>= 1) ss += __shfl_xor_sync(FULLMASK, ss, o);
    float rms = rsqrtf(ss * (1.0f / 64.0f) + 1.1920929e-7f);
    float v0 = v.x * rms, v1 = v.y * rms;
    float u0 = __shfl_xor_sync(FULLMASK, v0, 4);
    float u1 = __shfl_xor_sync(FULLMASK, v1, 4);
    int d0 = lane * 2;
    if (d0 < 8) {
        float c0, s0, c1, s1;
        rope_cs(t, d0, c0, s0);
        rope_cs(t, d0 + 1, c1, s1);
        v0 = v0 * c0 + u0 * s0;
        v1 = v1 * c1 + u1 * s1;
    } else if (d0 < 16) {
        float c0, s0, c1, s1;
        rope_cs(t, d0 - 8, c0, s0);
        rope_cs(t, d0 - 7, c1, s1);
        v0 = -v0 * c0 + u0 * s0;
        v1 = -v1 * c1 + u1 * s1;
    }
    *reinterpret_cast<float2*>(dst + lane * 2) = make_float2(v0 * scale, v1 * scale);
}

__global__ __launch_bounds__(256) void q_prep(
    const float* __restrict__ Qin, const float* __restrict__ qgain,
    float* __restrict__ Qout) {
    int warp = (blockIdx.x * 256 + threadIdx.x) >> 5;
    int lane = threadIdx.x & 31;
    if (warp >= B_ * T_ * NH_) return;
    int h = warp & 15;
    int t = (warp >> 4) & 2047;
    int b = warp >> 15;
    const float* src = Qin + ((size_t)(b * T_ + t)) * D_ + h * HD_;
    float* dst = Qout + (((size_t)(b * NH_ + h)) * T_ + t) * HD_;
    float scale = qgain[h] * 0.125f;
    norm_rope_row(src, dst, t, scale, lane);
}

__global__ __launch_bounds__(256) void kv_prep(
    const float* __restrict__ KVin,
    float* __restrict__ Kout, float* __restrict__ Vout) {
    int warp = (blockIdx.x * 256 + threadIdx.x) >> 5;
    int lane = threadIdx.x & 31;
    if (warp >= B_ * T_ * NKV_) return;
    int hk = warp & 3;
    int t = (warp >> 2) & 2047;
    int b = warp >> 13;
    const float* ksrc = KVin + ((size_t)(b * T_ + t)) * KV2_ + hk * HD_;
    float* kdst = Kout + (((size_t)(b * NKV_ + hk)) * T_ + t) * HD_;
    norm_rope_row(ksrc, kdst, t, 1.0f, lane);
    const float* vsrc = KVin + ((size_t)(b * T_ + t)) * KV2_ + KD_ + hk * HD_;
    float* vdst = Vout + (((size_t)(b * NKV_ + hk)) * T_ + t) * HD_;
    *reinterpret_cast<float2*>(vdst + lane * 2) =
        *reinterpret_cast<const float2*>(vsrc + lane * 2);
}

// ---------------- causal flash attention, fp32 via FFMA2 ----------------
// 64q x 64k tile, 128 threads (16 tx x 8 ty), 8 rows x 4 cols per thread
// (rows split: group0 = ty*4..+3, group1 = 32+ty*4..+3).
// smem: Qs[d][r] 16KB | Ks[d][c] 16KB | Vs[j][d] 16KB | Ps2[r][c] dup, stride 66
#define PSTRIDE 66
__global__ __launch_bounds__(128, 2) void attn_f2(
    const float* __restrict__ Qh, const float* __restrict__ Kh,
    const float* __restrict__ Vh, float* __restrict__ Y) {
    extern __shared__ char smraw[];
    float*  Qs  = reinterpret_cast<float*>(smraw);
    float*  Ks  = reinterpret_cast<float*>(smraw + 16384);
    float*  Vs  = reinterpret_cast<float*>(smraw + 32768);
    float2* Ps2 = reinterpret_cast<float2*>(smraw + 49152);  // 64*66*8 = 33792B
    int tid = threadIdx.x;
    int tx = tid & 15, ty = tid >> 4;   // ty 0..7
    int bh = blockIdx.y;
    int b = bh >> 4, h = bh & 15;
    int i0 = ((int)gridDim.x - 1 - (int)blockIdx.x) * 64;  // reversed for balance
    int kvh = h >> 2;
    const float* Qg = Qh + (((size_t)(b * NH_ + h)) * T_ + i0) * HD_;
    const float* Kg = Kh + ((size_t)(b * NKV_ + kvh)) * T_ * HD_;
    const float* Vg = Vh + ((size_t)(b * NKV_ + kvh)) * T_ * HD_;

    // load Q tile transposed: Qs[d][r]
#pragma unroll
    for (int tl = 0; tl < 8; tl++) {
        int idx = tid + tl * 128;             // float4 index 0..1023
        int r = idx >> 4, d4 = (idx & 15) << 2;
        float4 q4 = *reinterpret_cast<const float4*>(Qg + r * 64 + d4);
        Qs[(d4 + 0) * 64 + r] = q4.x; Qs[(d4 + 1) * 64 + r] = q4.y;
        Qs[(d4 + 2) * 64 + r] = q4.z; Qs[(d4 + 3) * 64 + r] = q4.w;
    }

    float m[2][4], l[2][4];
    ull acc2[2][4][2];   // [rowgroup][row][dpair] -- paired over output dims
#pragma unroll
    for (int g = 0; g < 2; g++)
#pragma unroll
        for (int i = 0; i < 4; i++) {
            m[g][i] = -1e30f; l[g][i] = 0.f;
            acc2[g][i][0] = 0ull; acc2[g][i][1] = 0ull;
        }

    int ntiles = i0 / 64 + 1;
    for (int kt = 0; kt < ntiles; kt++) {
        int j0 = kt * 64;
        __syncthreads();
#pragma unroll
        for (int tl = 0; tl < 8; tl++) {
            int idx = tid + tl * 128;
            int c = idx >> 4, d4 = (idx & 15) << 2;
            float4 k4 = *reinterpret_cast<const float4*>(Kg + (j0 + c) * 64 + d4);
            Ks[(d4 + 0) * 64 + c] = k4.x; Ks[(d4 + 1) * 64 + c] = k4.y;
            Ks[(d4 + 2) * 64 + c] = k4.z; Ks[(d4 + 3) * 64 + c] = k4.w;
            *reinterpret_cast<float4*>(Vs + idx * 4) =
                *reinterpret_cast<const float4*>(Vg + j0 * 64 + idx * 4);
        }
        __syncthreads();

        // S = Q K^T : s2[g][rp][j] pairs rows (2rp, 2rp+1) of group g, col tx*4+j
        ull s2[2][2][4];
#pragma unroll
        for (int g = 0; g < 2; g++)
#pragma unroll
            for (int rp = 0; rp < 2; rp++)
#pragma unroll
                for (int j = 0; j < 4; j++) s2[g][rp][j] = 0ull;
#pragma unroll 4
        for (int d = 0; d < 64; d++) {
            ulonglong2 qa = *reinterpret_cast<const ulonglong2*>(&Qs[d * 64 + ty * 4]);
            ulonglong2 qb = *reinterpret_cast<const ulonglong2*>(&Qs[d * 64 + 32 + ty * 4]);
            float4 k4 = *reinterpret_cast<const float4*>(&Ks[d * 64 + tx * 4]);
            ull kd[4] = {fdup2(k4.x), fdup2(k4.y), fdup2(k4.z), fdup2(k4.w)};
#pragma unroll
            for (int j = 0; j < 4; j++) {
                s2[0][0][j] = ffma2(qa.x, kd[j], s2[0][0][j]);
                s2[0][1][j] = ffma2(qa.y, kd[j], s2[0][1][j]);
                s2[1][0][j] = ffma2(qb.x, kd[j], s2[1][0][j]);
                s2[1][1][j] = ffma2(qb.y, kd[j], s2[1][1][j]);
            }
        }
        float s[2][4][4];
#pragma unroll
        for (int g = 0; g < 2; g++)
#pragma unroll
            for (int rp = 0; rp < 2; rp++)
#pragma unroll
                for (int j = 0; j < 4; j++)
                    funpack2(s[g][rp * 2][j], s[g][rp * 2 + 1][j], s2[g][rp][j]);

        if (j0 == i0) {  // diagonal tile: mask col > row
#pragma unroll
            for (int g = 0; g < 2; g++)
#pragma unroll
                for (int i = 0; i < 4; i++) {
                    int rloc = g * 32 + ty * 4 + i;
#pragma unroll
                    for (int j = 0; j < 4; j++)
                        if (tx * 4 + j > rloc) s[g][i][j] = -1e30f;
                }
        }

        // online softmax (per row; reduce across the 16 tx lanes)
#pragma unroll
        for (int g = 0; g < 2; g++)
#pragma unroll
            for (int i = 0; i < 4; i++) {
                float tmax = fmaxf(fmaxf(s[g][i][0], s[g][i][1]),
                                   fmaxf(s[g][i][2], s[g][i][3]));
#pragma unroll
                for (int o = 8; o; o >>= 1)
                    tmax = fmaxf(tmax, __shfl_xor_sync(FULLMASK, tmax, o));
                float mn = fmaxf(m[g][i], tmax);
                float sf = __expf(m[g][i] - mn);
                m[g][i] = mn;
                float r = 0.f;
#pragma unroll
                for (int j = 0; j < 4; j++) {
                    float p = __expf(s[g][i][j] - mn);
                    s[g][i][j] = p;
                    r += p;
                }
#pragma unroll
                for (int o = 8; o; o >>= 1) r += __shfl_xor_sync(FULLMASK, r, o);
                l[g][i] = l[g][i] * sf + r;
                ull sfd = fdup2(sf);
                acc2[g][i][0] = fmul2(acc2[g][i][0], sfd);
                acc2[g][i][1] = fmul2(acc2[g][i][1], sfd);
                int row = g * 32 + ty * 4 + i;
                float2* prow = &Ps2[row * PSTRIDE + tx * 4];
                prow[0] = make_float2(s[g][i][0], s[g][i][0]);
                prow[1] = make_float2(s[g][i][1], s[g][i][1]);
                prow[2] = make_float2(s[g][i][2], s[g][i][2]);
                prow[3] = make_float2(s[g][i][3], s[g][i][3]);
            }
        __syncthreads();

        // acc += P @ V: P read dup'd (broadcast), V natural d-pairs
#pragma unroll 2
        for (int jj2 = 0; jj2 < 32; jj2++) {
            int j = jj2 * 2;
            ulonglong2 va = *reinterpret_cast<const ulonglong2*>(&Vs[j * 64 + tx * 4]);
            ulonglong2 vb = *reinterpret_cast<const ulonglong2*>(&Vs[(j + 1) * 64 + tx * 4]);
#pragma unroll
            for (int g = 0; g < 2; g++)
#pragma unroll
                for (int i = 0; i < 4; i++) {
                    int row = g * 32 + ty * 4 + i;
                    ulonglong2 p = *reinterpret_cast<const ulonglong2*>(
                        &Ps2[row * PSTRIDE + j]);
                    acc2[g][i][0] = ffma2(p.x, va.x, acc2[g][i][0]);
                    acc2[g][i][1] = ffma2(p.x, va.y, acc2[g][i][1]);
                    acc2[g][i][0] = ffma2(p.y, vb.x, acc2[g][i][0]);
                    acc2[g][i][1] = ffma2(p.y, vb.y, acc2[g][i][1]);
                }
        }
    }

    // epilogue
#pragma unroll
    for (int g = 0; g < 2; g++)
#pragma unroll
        for (int i = 0; i < 4; i++) {
            float inv_l = 1.0f / l[g][i];
            int row = i0 + g * 32 + ty * 4 + i;
            float a0, a1, a2, a3;
            funpack2(a0, a1, acc2[g][i][0]);
            funpack2(a2, a3, acc2[g][i][1]);
            float4 o = make_float4(a0 * inv_l, a1 * inv_l, a2 * inv_l, a3 * inv_l);
            *reinterpret_cast<float4*>(
                Y + ((size_t)b * T_ + row) * D_ + h * HD_ + tx * 4) = o;
        }
}

// ---------------- launch ----------------
extern "C" void kernel_launch(void* const* d_in, const int* in_sizes, int n_in,
                              void* d_out, int out_size) {
    const float* x     = (const float*)d_in[0];
    const float* Wq    = (const float*)d_in[1];
    const float* Wk    = (const float*)d_in[2];
    const float* Wv    = (const float*)d_in[3];
    const float* Wproj = (const float*)d_in[4];
    const float* qg    = (const float*)d_in[5];
    const float* Aq    = (const float*)d_in[6];
    const float* Bq    = (const float*)d_in[7];
    const float* Av    = (const float*)d_in[8];
    const float* Bv    = (const float*)d_in[9];
    float* out = (float*)d_out;

    float *pWqe, *pWkv, *pq, *pkv, *pqh, *pkh, *pvh, *py;
    cudaGetSymbolAddress((void**)&pWqe, g_Wq_eff);
    cudaGetSymbolAddress((void**)&pWkv, g_Wkv);
    cudaGetSymbolAddress((void**)&pq, g_q);
    cudaGetSymbolAddress((void**)&pkv, g_kv);
    cudaGetSymbolAddress((void**)&pqh, g_qh);
    cudaGetSymbolAddress((void**)&pkh, g_kh);
    cudaGetSymbolAddress((void**)&pvh, g_vh);
    cudaGetSymbolAddress((void**)&py, g_y);

    // 1. fold LoRA / build combined weights
    lora_fuse<<<(D_ * D_) / 256, 256>>>(Wq, Bq, Aq, pWqe, D_, D_);
    build_wkv<<<(KV2_ * D_) / 256, 256>>>(Wk, Wv, Bv, Av, pWkv);

    // 2. projections (FFMA2 GEMM)
    dim3 gq(D_ / 128, (B_ * T_) / 128);
    dim3 gkv(KV2_ / 128, (B_ * T_) / 128);
    gemm_nt_f2<<<gq, 256>>>(x, pWqe, pq, B_ * T_, D_, D_);
    gemm_nt_f2<<<gkv, 256>>>(x, pWkv, pkv, B_ * T_, KV2_, D_);

    // 3. norm + rope + transpose
    q_prep<<<(B_ * T_ * NH_) / 8, 256>>>(pq, qg, pqh);
    kv_prep<<<(B_ * T_ * NKV_) / 8, 256>>>(pkv, pkh, pvh);

    // 4. attention (FFMA2 flash)
    cudaFuncSetAttribute(attn_f2,
                         cudaFuncAttributeMaxDynamicSharedMemorySize, 82944);
    dim3 ga(T_ / 64, B_ * NH_);
    attn_f2<<<ga, 128, 82944>>>(pqh, pkh, pvh, py);

    // 5. output projection
    gemm_nt_f2<<<gq, 256>>>(py, Wproj, out, B_ * T_, D_, D_);
}